// round 2
// baseline (speedup 1.0000x reference)
#include <cuda_runtime.h>
#include <cstdint>

// LZC48 over binary float spikes.
// Input:  [n_words, 48] float32 in {0.0, 1.0}, MSB first.
// Output: [n_words, 6]  float32, 6-bit MSB-first encoding of leading-zero count
//         (48 -> 110000 for an all-zero word).
//
// R2: DRAM fetch on this part is line-granular (128B/word measured), so the
// byte floor is 128B read + 24B write per word. This round removes the input
// smem staging, loads 2 words per thread directly into registers (4 independent
// LDG.128 via __ldcg), and keeps only coalesced output staging. Goal: raise
// achieved DRAM bandwidth from 79% toward ~90%.

constexpr int TPB = 256;            // threads per block
constexpr int W   = 2;              // words per thread
constexpr int WPB = TPB * W;        // 512 words per block

__device__ __forceinline__ int lzc_from_sector0(uint4 a, uint4 b,
                                                const uint4* __restrict__ wp)
{
    // 8-bit mask, bit7 = float0 (MSB first). Values are exactly 0.0f or 1.0f,
    // so nonzero bit pattern <=> 1.0f.
    unsigned m = (a.x ? 128u : 0u) | (a.y ? 64u : 0u) | (a.z ? 32u : 0u) | (a.w ? 16u : 0u)
               | (b.x ?   8u : 0u) | (b.y ?  4u : 0u) | (b.z ?  2u : 0u) | (b.w ?  1u : 0u);
    if (m)
        return __clz(m << 24);                  // 0..7
    // Rare fallback (P = 1/256): scan floats 8..47.
    unsigned long long acc = 0ull;
    #pragma unroll
    for (int i = 2; i < 12; i++) {
        uint4 v = __ldcg(wp + i);
        unsigned nib = (v.x ? 8u : 0u) | (v.y ? 4u : 0u)
                     | (v.z ? 2u : 0u) | (v.w ? 1u : 0u);
        acc = (acc << 4) | nib;                 // 40 bits; bit39 = float 8
    }
    return acc ? (8 + __clzll(acc << 24)) : 48;
}

__device__ __forceinline__ void encode6(float* __restrict__ so, int lzc)
{
    so[0] = (float)((lzc >> 5) & 1);
    so[1] = (float)((lzc >> 4) & 1);
    so[2] = (float)((lzc >> 3) & 1);
    so[3] = (float)((lzc >> 2) & 1);
    so[4] = (float)((lzc >> 1) & 1);
    so[5] = (float)( lzc       & 1);
}

__global__ __launch_bounds__(TPB)
void lzc48_kernel(const uint4* __restrict__ in4,   // word w at in4[w*12 .. w*12+11]
                  float* __restrict__ out,         // [n_words*6]
                  int n_words)
{
    __shared__ float sout[WPB * 6];                // 12 KB output staging

    const int tile = blockIdx.x * WPB;
    const int t    = threadIdx.x;
    int count = n_words - tile;
    if (count > WPB) count = WPB;

    const int w0 = tile + t;
    const int w1 = tile + t + TPB;
    const bool p0 = (t)       < count;
    const bool p1 = (t + TPB) < count;

    // Issue all 4 independent loads up front (2 x 16B halves per word; both
    // halves of a word sit in the same 128B line).
    uint4 a0, a1, b0, b1;
    const uint4* wp0 = in4 + (size_t)w0 * 12;
    const uint4* wp1 = in4 + (size_t)w1 * 12;
    if (p0) { a0 = __ldcg(wp0); a1 = __ldcg(wp0 + 1); }
    if (p1) { b0 = __ldcg(wp1); b1 = __ldcg(wp1 + 1); }

    if (p0) encode6(sout + (size_t)t * 6,         lzc_from_sector0(a0, a1, wp0));
    if (p1) encode6(sout + (size_t)(t + TPB) * 6, lzc_from_sector0(b0, b1, wp1));
    __syncthreads();

    // Coalesced write: 512*6 floats = 768 float4 per block.
    if (count == WPB) {
        float4* ob = reinterpret_cast<float4*>(out + (size_t)tile * 6);
        const float4* sb = reinterpret_cast<const float4*>(sout);
        #pragma unroll
        for (int k = 0; k < 3; k++)
            ob[k * TPB + t] = sb[k * TPB + t];
    } else {
        for (int j = t; j < count * 6; j += TPB)
            out[(size_t)tile * 6 + j] = sout[j];
    }
}

extern "C" void kernel_launch(void* const* d_in, const int* in_sizes, int n_in,
                              void* d_out, int out_size)
{
    const uint4* in4 = (const uint4*)d_in[0];
    float* out = (float*)d_out;
    const int n_words = in_sizes[0] / 48;          // 2,097,152
    const int grid = (n_words + WPB - 1) / WPB;    // 4096
    lzc48_kernel<<<grid, TPB>>>(in4, out, n_words);
}